// round 13
// baseline (speedup 1.0000x reference)
#include <cuda_runtime.h>

#define D 128
#define N_MAX 100000
#define A_MAX 4096
#define S_MAX 512
#define TEMP_INV 10.0f
#define QS 300.0f          // int8 quantization scale for normalized features
// exp(p*TEMP_INV/QS^2) == 2^(p * KE2)
#define KE2 (TEMP_INV / (QS * QS) * 1.44269504088896f)

// Scratch (allocation-free rule: __device__ globals)
__device__ uint4         g_q8[N_MAX * 8];  // normalized rows, int8 x128, 128 B/row
__device__ unsigned char g_lab[N_MAX];     // labels 0..9
__device__ float         g_loss[A_MAX];
__device__ unsigned int  g_ctr;            // zero-init; self-resetting

__device__ __forceinline__ int q8(float v) {
    int q = __float2int_rn(v * QS);
    return max(-127, min(127, q));
}

// ---------------------------------------------------------------------------
// Kernel 1: normalize rows -> int8 (scale QS), store labels. 4 rows/warp.
// ---------------------------------------------------------------------------
__global__ __launch_bounds__(256)
void prep_kernel(const float* __restrict__ x,
                 const int* __restrict__ y, int N) {
    int gw   = (blockIdx.x * blockDim.x + threadIdx.x) >> 5;
    int lane = threadIdx.x & 31;
    int base = gw * 4;
    if (base >= N) return;

    float4 v[4];
    float  s[4];
#pragma unroll
    for (int r = 0; r < 4; ++r) {
        int row = base + r;
        v[r] = (row < N) ? __ldg((const float4*)(x + (size_t)row * D) + lane)
                         : make_float4(1.f, 0.f, 0.f, 0.f);
        s[r] = v[r].x * v[r].x + v[r].y * v[r].y + v[r].z * v[r].z + v[r].w * v[r].w;
    }
#pragma unroll
    for (int o = 16; o > 0; o >>= 1) {
#pragma unroll
        for (int r = 0; r < 4; ++r)
            s[r] += __shfl_xor_sync(0xffffffffu, s[r], o);
    }
#pragma unroll
    for (int r = 0; r < 4; ++r) {
        int row = base + r;
        if (row < N) {
            float rn = rsqrtf(s[r]);
            int q0 = q8(v[r].x * rn), q1 = q8(v[r].y * rn);
            int q2 = q8(v[r].z * rn), q3 = q8(v[r].w * rn);
            unsigned int p = (unsigned int)(q0 & 0xff)
                           | ((unsigned int)(q1 & 0xff) << 8)
                           | ((unsigned int)(q2 & 0xff) << 16)
                           | ((unsigned int)(q3 & 0xff) << 24);
            ((unsigned int*)g_q8)[(size_t)row * 32 + lane] = p;
        }
    }
    if (lane < 4 && base + lane < N)
        g_lab[base + lane] = (unsigned char)__ldg(y + base + lane);
}

// ---------------------------------------------------------------------------
// Kernel 2: one block per anchor + fused deterministic final reduction.
// Staging packs the positive mask into bit 31 of each index AND counts the
// positives (shared int atomic — exact/deterministic), so the inner loop is:
// LDS + LDG.128 + 4 DP4A + 1 REDUX + I2F/FMUL/EX2 + 2 FADD-ish. No cnt, no
// label gather, no branch. launch_bounds(256,6) leaves ~42 regs so ptxas can
// keep ~6 gathers in flight.
// ---------------------------------------------------------------------------
__global__ __launch_bounds__(256, 6)
void loss_kernel(const int* __restrict__ anchors,
                 const int* __restrict__ sampled, int S,
                 float* __restrict__ out) {
    __shared__ int   s_aq[32];       // anchor row, 32 x u32 (packed int8)
    __shared__ int   sidx[S_MAX];    // bit31 = positive flag, bits 0..30 = index
    __shared__ float s_num[8], s_den[8];
    __shared__ int   s_tc;           // positives per anchor (exact)
    __shared__ int   s_done;
    __shared__ float s_red[256];

    int a    = blockIdx.x;
    int tid  = threadIdx.x;
    int lane = tid & 31;
    int w    = tid >> 5;
    int hl   = lane & 7;             // lane within 8-group
    int sub  = lane >> 3;            // which of 4 samples

    int aidx = __ldg(anchors + a);
    unsigned char ya = g_lab[aidx];

    if (tid == 0) s_tc = 0;
    if (tid < 32)
        s_aq[tid] = ((const int*)g_q8)[(size_t)aidx * 32 + tid];
    __syncthreads();                 // s_tc=0 visible before atomics

    // stage indices (int4-wide), fold label compare into sign bit, count pos
    {
        int pcnt = 0;
        for (int i = tid; i < (S >> 2); i += blockDim.x) {
            int4 sv = __ldg((const int4*)(sampled + (size_t)a * S) + i);
            int p0 = (g_lab[sv.x] == ya);
            int p1 = (g_lab[sv.y] == ya);
            int p2 = (g_lab[sv.z] == ya);
            int p3 = (g_lab[sv.w] == ya);
            sidx[i * 4 + 0] = sv.x | (p0 << 31);
            sidx[i * 4 + 1] = sv.y | (p1 << 31);
            sidx[i * 4 + 2] = sv.z | (p2 << 31);
            sidx[i * 4 + 3] = sv.w | (p3 << 31);
            pcnt += p0 + p1 + p2 + p3;
        }
#pragma unroll
        for (int o = 16; o > 0; o >>= 1)
            pcnt += __shfl_xor_sync(0xffffffffu, pcnt, o);
        if (lane == 0 && pcnt) atomicAdd(&s_tc, pcnt);   // int: exact, deterministic
    }
    __syncthreads();

    // per-lane anchor slice: 16 consecutive dims = 4 packed ints
    int aq0 = s_aq[hl * 4 + 0], aq1 = s_aq[hl * 4 + 1];
    int aq2 = s_aq[hl * 4 + 2], aq3 = s_aq[hl * 4 + 3];

    float num = 0.f, den = 0.f;
    unsigned int gmask = 0xffu << (sub * 8);   // this lane's 8-lane group

    int per = S >> 3;                // 64 samples per warp
    int s0  = w * per;
#pragma unroll 8
    for (int i = 0; i < per; i += 4) {
        int sp = sidx[s0 + i + sub];
        int si = sp & 0x7fffffff;
        uint4 v = __ldg(&g_q8[(size_t)si * 8 + hl]);   // 16 int8, coalesced
        int p;
        p = __dp4a((int)v.x, aq0, 0);
        p = __dp4a((int)v.y, aq1, p);
        p = __dp4a((int)v.z, aq2, p);
        p = __dp4a((int)v.w, aq3, p);
        p = __reduce_add_sync(gmask, p);               // 8-lane group sum
        float fp = (float)p * KE2;
        float e;
        asm("ex2.approx.ftz.f32 %0, %1;" : "=f"(e) : "f"(fp));
        den += e;
        num += (sp < 0) ? e : 0.f;
    }

    // full 32-lane reduce; each sample was counted 8x (once per group lane)
#pragma unroll
    for (int o = 16; o > 0; o >>= 1) {
        num += __shfl_xor_sync(0xffffffffu, num, o);
        den += __shfl_xor_sync(0xffffffffu, den, o);
    }
    if (lane == 0) {
        s_num[w] = num * 0.125f;     // exact: /8
        s_den[w] = den * 0.125f;
    }
    __syncthreads();

    if (tid == 0) {
        float tn = 0.f, td = 0.f;
#pragma unroll
        for (int i = 0; i < 8; ++i) { tn += s_num[i]; td += s_den[i]; }
        int   tc = s_tc;
        float loss = 0.f;
        if (tc > 0)
            loss = (logf(td) - logf(tn)) / (float)tc;   // = -log(num/den)/cnt
        g_loss[a] = loss;
        __threadfence();                         // publish g_loss
        unsigned int t = atomicAdd(&g_ctr, 1u);
        s_done = (t == gridDim.x - 1) ? 1 : 0;
    }
    __syncthreads();

    // Last block sums in fixed order -> bit-deterministic.
    if (s_done) {
        int A = gridDim.x;
        float s = 0.f;
        for (int i = tid; i < A; i += 256)
            s += __ldcg(&g_loss[i]);             // bypass L1 (cross-SM data)
        s_red[tid] = s;
        __syncthreads();
#pragma unroll
        for (int o = 128; o > 0; o >>= 1) {
            if (tid < o) s_red[tid] += s_red[tid + o];
            __syncthreads();
        }
        if (tid == 0) {
            out[0] = s_red[0];
            g_ctr  = 0;                          // reset for next graph replay
        }
    }
}

// ---------------------------------------------------------------------------
extern "C" void kernel_launch(void* const* d_in, const int* in_sizes, int n_in,
                              void* d_out, int out_size) {
    const float* x       = (const float*)d_in[0];
    const int*   y       = (const int*)d_in[1];
    const int*   anchors = (const int*)d_in[2];
    const int*   sampled = (const int*)d_in[3];
    float*       out     = (float*)d_out;

    int N = in_sizes[1];                 // 100000
    int A = in_sizes[2];                 // 4096
    int S = in_sizes[3] / A;             // 512

    // 1) normalize -> int8 + labels (32 rows per 256-thread block)
    int rows_per_block = 32;
    int pblocks = (N + rows_per_block - 1) / rows_per_block;
    prep_kernel<<<pblocks, 256>>>(x, y, N);

    // 2) per-anchor loss + fused deterministic reduction
    loss_kernel<<<A, 256>>>(anchors, sampled, S, out);
}

// round 15
// speedup vs baseline: 1.5067x; 1.5067x over previous
#include <cuda_runtime.h>

#define D 128
#define N_MAX 100000
#define A_MAX 4096
#define S_MAX 512
#define TEMP_INV 10.0f
#define QS 300.0f          // int8 quantization scale for normalized features
// exp(p*TEMP_INV/QS^2) == 2^(p * KE2)
#define KE2 (TEMP_INV / (QS * QS) * 1.44269504088896f)

// Scratch (allocation-free rule: __device__ globals)
__device__ uint4         g_q8[N_MAX * 8];  // normalized rows, int8 x128, 128 B/row
__device__ unsigned char g_lab[N_MAX];     // labels 0..9
__device__ float         g_loss[A_MAX];
__device__ unsigned int  g_ctr;            // zero-init; self-resetting

__device__ __forceinline__ int q8(float v) {
    int q = __float2int_rn(v * QS);
    return max(-127, min(127, q));
}

// ---------------------------------------------------------------------------
// Kernel 1: normalize rows -> int8 (scale QS), store labels. 8 rows/warp
// (8 front-batched LDG.128 -> MLP=8 to push DRAM% up).
// ---------------------------------------------------------------------------
__global__ __launch_bounds__(256)
void prep_kernel(const float* __restrict__ x,
                 const int* __restrict__ y, int N) {
    int gw   = (blockIdx.x * blockDim.x + threadIdx.x) >> 5;
    int lane = threadIdx.x & 31;
    int base = gw * 8;
    if (base >= N) return;

    float4 v[8];
    float  s[8];
#pragma unroll
    for (int r = 0; r < 8; ++r) {
        int row = base + r;
        v[r] = (row < N) ? __ldg((const float4*)(x + (size_t)row * D) + lane)
                         : make_float4(1.f, 0.f, 0.f, 0.f);
    }
#pragma unroll
    for (int r = 0; r < 8; ++r)
        s[r] = v[r].x * v[r].x + v[r].y * v[r].y + v[r].z * v[r].z + v[r].w * v[r].w;
#pragma unroll
    for (int o = 16; o > 0; o >>= 1) {
#pragma unroll
        for (int r = 0; r < 8; ++r)
            s[r] += __shfl_xor_sync(0xffffffffu, s[r], o);
    }
#pragma unroll
    for (int r = 0; r < 8; ++r) {
        int row = base + r;
        if (row < N) {
            float rn = rsqrtf(s[r]);
            int q0 = q8(v[r].x * rn), q1 = q8(v[r].y * rn);
            int q2 = q8(v[r].z * rn), q3 = q8(v[r].w * rn);
            unsigned int p = (unsigned int)(q0 & 0xff)
                           | ((unsigned int)(q1 & 0xff) << 8)
                           | ((unsigned int)(q2 & 0xff) << 16)
                           | ((unsigned int)(q3 & 0xff) << 24);
            ((unsigned int*)g_q8)[(size_t)row * 32 + lane] = p;
        }
    }
    if (lane < 8 && base + lane < N)
        g_lab[base + lane] = (unsigned char)__ldg(y + base + lane);
}

// ---------------------------------------------------------------------------
// Kernel 2: one block per anchor + fused deterministic final reduction.
// R8-proven inner loop: LDS + LDG.128 + 4 DP4A + 3 SHFL + EX2, branchless,
// 8-way redundant accumulation (exact /8 at the end). Staging pre-folds the
// positive mask into bit31 AND pre-scales the index to a BYTE OFFSET (si<<7),
// removing the per-iteration address IMAD. cnt is computed at staging.
// ---------------------------------------------------------------------------
__global__ __launch_bounds__(256, 7)
void loss_kernel(const int* __restrict__ anchors,
                 const int* __restrict__ sampled, int S,
                 float* __restrict__ out) {
    __shared__ int   s_aq[32];       // anchor row, 32 x u32 (packed int8)
    __shared__ int   sidx[S_MAX];    // bit31 = pos flag, bits 0..30 = byte offset
    __shared__ float s_num[8], s_den[8];
    __shared__ int   s_tc;           // positives per anchor (exact)
    __shared__ int   s_done;
    __shared__ float s_red[256];

    int a    = blockIdx.x;
    int tid  = threadIdx.x;
    int lane = tid & 31;
    int w    = tid >> 5;
    int hl   = lane & 7;             // lane within 8-group
    int sub  = lane >> 3;            // which of 4 samples

    int aidx = __ldg(anchors + a);
    unsigned char ya = g_lab[aidx];

    if (tid == 0) s_tc = 0;
    if (tid < 32)
        s_aq[tid] = ((const int*)g_q8)[(size_t)aidx * 32 + tid];
    __syncthreads();                 // s_tc=0 visible before atomics

    // stage byte offsets (int4-wide), fold label compare into sign bit, count
    {
        int pcnt = 0;
        for (int i = tid; i < (S >> 2); i += blockDim.x) {
            int4 sv = __ldg((const int4*)(sampled + (size_t)a * S) + i);
            int p0 = (g_lab[sv.x] == ya);
            int p1 = (g_lab[sv.y] == ya);
            int p2 = (g_lab[sv.z] == ya);
            int p3 = (g_lab[sv.w] == ya);
            sidx[i * 4 + 0] = (sv.x << 7) | (p0 << 31);
            sidx[i * 4 + 1] = (sv.y << 7) | (p1 << 31);
            sidx[i * 4 + 2] = (sv.z << 7) | (p2 << 31);
            sidx[i * 4 + 3] = (sv.w << 7) | (p3 << 31);
            pcnt += p0 + p1 + p2 + p3;
        }
#pragma unroll
        for (int o = 16; o > 0; o >>= 1)
            pcnt += __shfl_xor_sync(0xffffffffu, pcnt, o);
        if (lane == 0 && pcnt) atomicAdd(&s_tc, pcnt);   // int: exact, deterministic
    }
    __syncthreads();

    // per-lane anchor slice: 16 consecutive dims = 4 packed ints
    int aq0 = s_aq[hl * 4 + 0], aq1 = s_aq[hl * 4 + 1];
    int aq2 = s_aq[hl * 4 + 2], aq3 = s_aq[hl * 4 + 3];

    const char* rowbase = (const char*)g_q8 + hl * 16;   // lane's 16B slice
    float num = 0.f, den = 0.f;

    int per = S >> 3;                // 64 samples per warp
    int s0  = w * per;
#pragma unroll 8
    for (int i = 0; i < per; i += 4) {
        int sp  = sidx[s0 + i + sub];
        int off = sp & 0x7fffffff;   // byte offset of the row
        uint4 v = __ldg((const uint4*)(rowbase + off));  // 16 int8, coalesced
        int p;
        p = __dp4a((int)v.x, aq0, 0);
        p = __dp4a((int)v.y, aq1, p);
        p = __dp4a((int)v.z, aq2, p);
        p = __dp4a((int)v.w, aq3, p);
        p += __shfl_xor_sync(0xffffffffu, p, 4);
        p += __shfl_xor_sync(0xffffffffu, p, 2);
        p += __shfl_xor_sync(0xffffffffu, p, 1);
        float fp = (float)p * KE2;
        float e;
        asm("ex2.approx.ftz.f32 %0, %1;" : "=f"(e) : "f"(fp));
        den += e;
        num += (sp < 0) ? e : 0.f;
    }

    // full 32-lane reduce; each sample was counted 8x (once per group lane)
#pragma unroll
    for (int o = 16; o > 0; o >>= 1) {
        num += __shfl_xor_sync(0xffffffffu, num, o);
        den += __shfl_xor_sync(0xffffffffu, den, o);
    }
    if (lane == 0) {
        s_num[w] = num * 0.125f;     // exact: /8
        s_den[w] = den * 0.125f;
    }
    __syncthreads();

    if (tid == 0) {
        float tn = 0.f, td = 0.f;
#pragma unroll
        for (int i = 0; i < 8; ++i) { tn += s_num[i]; td += s_den[i]; }
        int   tc = s_tc;
        float loss = 0.f;
        if (tc > 0)
            loss = (logf(td) - logf(tn)) / (float)tc;   // = -log(num/den)/cnt
        g_loss[a] = loss;
        __threadfence();                         // publish g_loss
        unsigned int t = atomicAdd(&g_ctr, 1u);
        s_done = (t == gridDim.x - 1) ? 1 : 0;
    }
    __syncthreads();

    // Last block sums in fixed order -> bit-deterministic.
    if (s_done) {
        int A = gridDim.x;
        float s = 0.f;
        for (int i = tid; i < A; i += 256)
            s += __ldcg(&g_loss[i]);             // bypass L1 (cross-SM data)
        s_red[tid] = s;
        __syncthreads();
#pragma unroll
        for (int o = 128; o > 0; o >>= 1) {
            if (tid < o) s_red[tid] += s_red[tid + o];
            __syncthreads();
        }
        if (tid == 0) {
            out[0] = s_red[0];
            g_ctr  = 0;                          // reset for next graph replay
        }
    }
}

// ---------------------------------------------------------------------------
extern "C" void kernel_launch(void* const* d_in, const int* in_sizes, int n_in,
                              void* d_out, int out_size) {
    const float* x       = (const float*)d_in[0];
    const int*   y       = (const int*)d_in[1];
    const int*   anchors = (const int*)d_in[2];
    const int*   sampled = (const int*)d_in[3];
    float*       out     = (float*)d_out;

    int N = in_sizes[1];                 // 100000
    int A = in_sizes[2];                 // 4096
    int S = in_sizes[3] / A;             // 512

    // 1) normalize -> int8 + labels (64 rows per 256-thread block)
    int rows_per_block = 64;
    int pblocks = (N + rows_per_block - 1) / rows_per_block;
    prep_kernel<<<pblocks, 256>>>(x, y, N);

    // 2) per-anchor loss + fused deterministic reduction
    loss_kernel<<<A, 256>>>(anchors, sampled, S, out);
}